// round 4
// baseline (speedup 1.0000x reference)
#include <cuda_runtime.h>

#define N_NODES 100000
#define N_EDGES 3200000
#define FEAT 16

// Scratch in __device__ globals (no allocations allowed).
__device__ int    g_degi   [N_NODES];
__device__ int    g_rowstart[N_NODES + 1];
__device__ int    g_cursor [N_NODES];
__device__ int    g_blocksums[512];
__device__ int    g_esrc   [N_EDGES];        // src ids sorted by dst
__device__ float  g_dinv   [N_NODES];
__device__ float4 g_hs1    [N_NODES * 4];    // layer1 transformed+src-scaled features
__device__ float4 g_agg1   [N_NODES * 4];
__device__ float4 g_hs2    [N_NODES * 4];

// ---------------------------------------------------------------- degree ----
__global__ void k_zero(int n) {
    int i = blockIdx.x * blockDim.x + threadIdx.x;
    if (i < n) g_degi[i] = 0;
}

__global__ void k_hist(const int* __restrict__ dst, int E) {
    int e = blockIdx.x * blockDim.x + threadIdx.x;
    if (e < E) atomicAdd(&g_degi[dst[e]], 1);
}

// ----------------------------------------------------------------- scan -----
__global__ void k_scanA(int n) {
    __shared__ int sh[256];
    int t = threadIdx.x;
    int idx = blockIdx.x * 256 + t;
    int val = (idx < n) ? g_degi[idx] : 0;
    sh[t] = val;
    __syncthreads();
#pragma unroll
    for (int off = 1; off < 256; off <<= 1) {
        int v = (t >= off) ? sh[t - off] : 0;
        __syncthreads();
        sh[t] += v;
        __syncthreads();
    }
    if (idx < n) g_rowstart[idx] = sh[t] - val;   // block-local exclusive
    if (t == 255) g_blocksums[blockIdx.x] = sh[255];
}

__global__ void k_scanB(int nb) {
    __shared__ int sh[512];
    int t = threadIdx.x;
    int v = (t < nb) ? g_blocksums[t] : 0;
    sh[t] = v;
    __syncthreads();
#pragma unroll
    for (int off = 1; off < 512; off <<= 1) {
        int u = (t >= off) ? sh[t - off] : 0;
        __syncthreads();
        sh[t] += u;
        __syncthreads();
    }
    if (t < nb) g_blocksums[t] = sh[t] - v;       // exclusive block offsets
}

__global__ void k_scanC(int n, int E) {
    int idx = blockIdx.x * blockDim.x + threadIdx.x;
    if (idx < n) {
        int r = g_rowstart[idx] + g_blocksums[idx >> 8];
        g_rowstart[idx] = r;
        g_cursor[idx]   = r;
    }
    if (idx == 0) g_rowstart[n] = E;
}

// ----------------------------------------------------------------- bucket ---
__global__ void k_bucket(const int* __restrict__ src,
                         const int* __restrict__ dst, int E) {
    int e = blockIdx.x * blockDim.x + threadIdx.x;
    if (e >= E) return;
    int d = dst[e];
    int pos = atomicAdd(&g_cursor[d], 1);
    g_esrc[pos] = src[e];
}

// ---------------------------------------------------------- layer 1 xform ----
__global__ void k_transform1(const float* __restrict__ x,
                             const float* __restrict__ W, int n) {
    __shared__ float sW[16][16];
    int t = threadIdx.x;
    if (t < 256) sW[t >> 4][t & 15] = W[t];
    __syncthreads();

    int i = blockIdx.x * blockDim.x + t;
    if (i >= n) return;

    float di = rsqrtf((float)g_degi[i] + 1.0f);   // +1 self loop
    g_dinv[i] = di;

    const float4* xr = (const float4*)(x + (size_t)i * FEAT);
    float xin[16];
#pragma unroll
    for (int q = 0; q < 4; q++) {
        float4 v = xr[q];
        xin[4*q+0] = v.x; xin[4*q+1] = v.y; xin[4*q+2] = v.z; xin[4*q+3] = v.w;
    }

    float4* hp = &g_hs1[(size_t)i * 4];
#pragma unroll
    for (int qq = 0; qq < 4; qq++) {
        float4 o;
        float* op = &o.x;
#pragma unroll
        for (int jj = 0; jj < 4; jj++) {
            int j = 4*qq + jj;
            float s = 0.0f;
#pragma unroll
            for (int k = 0; k < 16; k++) s = fmaf(xin[k], sW[k][j], s);
            op[jj] = s * di;
        }
        hp[qq] = o;
    }
}

// ------------------------------------------------------------- aggregate ----
// One warp per node. Lanes split 8 edge-slots x 4 feature-quarters.
// Register accumulation + shfl reduction; exactly one 64B write per node.
template <int LAYER>
__global__ void k_agg(const float* __restrict__ b2,
                      float* __restrict__ out, int n) {
    int gw   = (blockIdx.x * blockDim.x + threadIdx.x) >> 5;
    int lane = threadIdx.x & 31;
    if (gw >= n) return;
    int q    = lane & 3;
    int slot = lane >> 2;

    int beg = g_rowstart[gw];
    int end = g_rowstart[gw + 1];
    const float4* hs = (LAYER == 1) ? g_hs1 : g_hs2;

    float4 acc = make_float4(0.f, 0.f, 0.f, 0.f);
    for (int j = beg + slot; j < end; j += 8) {
        int s = __ldg(&g_esrc[j]);
        float4 v = __ldg(&hs[(size_t)s * 4 + q]);
        acc.x += v.x; acc.y += v.y; acc.z += v.z; acc.w += v.w;
    }
#pragma unroll
    for (int off = 16; off >= 4; off >>= 1) {
        acc.x += __shfl_down_sync(0xffffffffu, acc.x, off);
        acc.y += __shfl_down_sync(0xffffffffu, acc.y, off);
        acc.z += __shfl_down_sync(0xffffffffu, acc.z, off);
        acc.w += __shfl_down_sync(0xffffffffu, acc.w, off);
    }
    if (lane < 4) {
        float4 self = hs[(size_t)gw * 4 + lane];
        acc.x += self.x; acc.y += self.y; acc.z += self.z; acc.w += self.w;
        if (LAYER == 1) {
            g_agg1[(size_t)gw * 4 + lane] = acc;
        } else {
            float di = g_dinv[gw];
            float4 bb = __ldg(((const float4*)b2) + lane);
            acc.x = fmaf(acc.x, di, bb.x);
            acc.y = fmaf(acc.y, di, bb.y);
            acc.z = fmaf(acc.z, di, bb.z);
            acc.w = fmaf(acc.w, di, bb.w);
            ((float4*)out)[(size_t)gw * 4 + lane] = acc;
        }
    }
}

// ------------------------------------------- layer1 epilogue + layer2 xform -
__global__ void k_transform2(const float* __restrict__ W2,
                             const float* __restrict__ b1, int n) {
    __shared__ float sW[16][16];
    __shared__ float sb[16];
    int t = threadIdx.x;
    if (t < 256) sW[t >> 4][t & 15] = W2[t];
    if (t < 16) sb[t] = b1[t];
    __syncthreads();

    int i = blockIdx.x * blockDim.x + t;
    if (i >= n) return;

    float di = g_dinv[i];
    const float4* ap1 = &g_agg1[(size_t)i * 4];
    float hin[16];
#pragma unroll
    for (int q = 0; q < 4; q++) {
        float4 v = ap1[q];
        hin[4*q+0] = v.x; hin[4*q+1] = v.y; hin[4*q+2] = v.z; hin[4*q+3] = v.w;
    }
#pragma unroll
    for (int k = 0; k < 16; k++)
        hin[k] = fmaxf(fmaf(hin[k], di, sb[k]), 0.0f);   // *dinv + b1, relu

    float4* hp = &g_hs2[(size_t)i * 4];
#pragma unroll
    for (int qq = 0; qq < 4; qq++) {
        float4 o;
        float* op = &o.x;
#pragma unroll
        for (int jj = 0; jj < 4; jj++) {
            int j = 4*qq + jj;
            float s = 0.0f;
#pragma unroll
            for (int k = 0; k < 16; k++) s = fmaf(hin[k], sW[k][j], s);
            op[jj] = s * di;
        }
        hp[qq] = o;
    }
}

// ---------------------------------------------------------------- launch ----
extern "C" void kernel_launch(void* const* d_in, const int* in_sizes, int n_in,
                              void* d_out, int out_size) {
    const float* x    = (const float*)d_in[0];
    const int*   eidx = (const int*)  d_in[1];
    const float* W1   = (const float*)d_in[2];
    const float* b1   = (const float*)d_in[3];
    const float* W2   = (const float*)d_in[4];
    const float* b2   = (const float*)d_in[5];
    float* out = (float*)d_out;

    int n = in_sizes[0] / FEAT;       // 100000
    int E = in_sizes[1] / 2;          // 3200000
    const int* src = eidx;
    const int* dst = eidx + E;

    const int B = 256;
    int gn  = (n + B - 1) / B;        // node-parallel grid
    int ge  = (E + B - 1) / B;        // edge-parallel grid
    int nb  = gn;                      // #scan blocks (<=512)
    int gw  = (n * 32 + B - 1) / B;   // warp-per-node grid

    // CSR build (once, shared by both layers)
    k_zero  <<<gn, B>>>(n);
    k_hist  <<<ge, B>>>(dst, E);
    k_scanA <<<nb, 256>>>(n);
    k_scanB <<<1, 512>>>(nb);
    k_scanC <<<gn, B>>>(n, E);
    k_bucket<<<ge, B>>>(src, dst, E);

    // Layer 1
    k_transform1<<<gn, B>>>(x, W1, n);
    k_agg<1>    <<<gw, B>>>(nullptr, nullptr, n);
    // Layer 2 (epilogue fused into aggregate)
    k_transform2<<<gn, B>>>(W2, b1, n);
    k_agg<2>    <<<gw, B>>>(b2, out, n);
}

// round 6
// speedup vs baseline: 1.0073x; 1.0073x over previous
#include <cuda_runtime.h>

#define N_NODES 100000
#define N_EDGES 3200000
#define FEAT 16
#define CHUNK 16

// Scratch in __device__ globals (no allocations allowed).
__device__ int    g_degi    [N_NODES];
__device__ int    g_scantmp [N_NODES];
__device__ int    g_cursor  [N_NODES];
__device__ int    g_blocksums[512];
__device__ int2   g_edges   [N_EDGES];       // (src,dst) sorted by dst
__device__ float  g_dinv    [N_NODES];
__device__ float4 g_hs1     [N_NODES * 4];
__device__ float4 g_agg1    [N_NODES * 4];
__device__ float4 g_hs2     [N_NODES * 4];
__device__ float4 g_agg2    [N_NODES * 4];

__device__ __forceinline__ void red_add_v4(float4* p, float4 v) {
    asm volatile("red.global.add.v4.f32 [%0], {%1, %2, %3, %4};"
                 :: "l"(p), "f"(v.x), "f"(v.y), "f"(v.z), "f"(v.w)
                 : "memory");
}

// ---------------------------------------------------------------- degree ----
__global__ void k_zero(int n) {
    int i = blockIdx.x * blockDim.x + threadIdx.x;
    if (i < n) g_degi[i] = 0;
}

__global__ void k_hist(const int* __restrict__ dst, int E) {
    int e = blockIdx.x * blockDim.x + threadIdx.x;
    if (e < E) atomicAdd(&g_degi[dst[e]], 1);
}

// ----------------------------------------------------------------- scan -----
__global__ void k_scanA(int n) {
    __shared__ int sh[256];
    int t = threadIdx.x;
    int idx = blockIdx.x * 256 + t;
    int val = (idx < n) ? g_degi[idx] : 0;
    sh[t] = val;
    __syncthreads();
#pragma unroll
    for (int off = 1; off < 256; off <<= 1) {
        int v = (t >= off) ? sh[t - off] : 0;
        __syncthreads();
        sh[t] += v;
        __syncthreads();
    }
    if (idx < n) g_scantmp[idx] = sh[t] - val;    // block-local exclusive
    if (t == 255) g_blocksums[blockIdx.x] = sh[255];
}

__global__ void k_scanB(int nb) {
    __shared__ int sh[512];
    int t = threadIdx.x;
    int v = (t < nb) ? g_blocksums[t] : 0;
    sh[t] = v;
    __syncthreads();
#pragma unroll
    for (int off = 1; off < 512; off <<= 1) {
        int u = (t >= off) ? sh[t - off] : 0;
        __syncthreads();
        sh[t] += u;
        __syncthreads();
    }
    if (t < nb) g_blocksums[t] = sh[t] - v;       // exclusive block offsets
}

__global__ void k_scanC(int n) {
    int idx = blockIdx.x * blockDim.x + threadIdx.x;
    if (idx < n)
        g_cursor[idx] = g_scantmp[idx] + g_blocksums[idx >> 8];
}

// ----------------------------------------------------------------- bucket ---
__global__ void k_bucket(const int* __restrict__ src,
                         const int* __restrict__ dst, int E) {
    int e = blockIdx.x * blockDim.x + threadIdx.x;
    if (e >= E) return;
    int d = dst[e];
    int pos = atomicAdd(&g_cursor[d], 1);
    g_edges[pos] = make_int2(src[e], d);
}

// ---------------------------------------------------------- layer 1 xform ----
__global__ void k_transform1(const float* __restrict__ x,
                             const float* __restrict__ W, int n) {
    __shared__ float sW[16][16];
    int t = threadIdx.x;
    if (t < 256) sW[t >> 4][t & 15] = W[t];
    __syncthreads();

    int i = blockIdx.x * blockDim.x + t;
    if (i >= n) return;

    float di = rsqrtf((float)g_degi[i] + 1.0f);   // +1 self loop
    g_dinv[i] = di;

    const float4* xr = (const float4*)(x + (size_t)i * FEAT);
    float xin[16];
#pragma unroll
    for (int q = 0; q < 4; q++) {
        float4 v = xr[q];
        xin[4*q+0] = v.x; xin[4*q+1] = v.y; xin[4*q+2] = v.z; xin[4*q+3] = v.w;
    }

    float4* hp = &g_hs1[(size_t)i * 4];
    float4* ap = &g_agg1[(size_t)i * 4];
#pragma unroll
    for (int qq = 0; qq < 4; qq++) {
        float4 o;
        float* op = &o.x;
#pragma unroll
        for (int jj = 0; jj < 4; jj++) {
            int j = 4*qq + jj;
            float s = 0.0f;
#pragma unroll
            for (int k = 0; k < 16; k++) s = fmaf(xin[k], sW[k][j], s);
            op[jj] = s * di;
        }
        hp[qq] = o;
        ap[qq] = o;   // self-loop init
    }
}

// -------------------------------------------------- segmented aggregation ---
// 4 lanes (q=0..3) cooperate on one CHUNK-long slice of the dst-sorted edge
// list. Runs of equal dst are accumulated in registers. Runs touching a
// chunk boundary flush with red.v4 (self already in init); strictly interior
// runs own their dst exclusively -> plain store of sum+self.
template <int LAYER>
__global__ void k_aggseg(int E) {
    int t   = blockIdx.x * blockDim.x + threadIdx.x;
    int grp = t >> 2;
    int q   = t & 3;
    int j0  = grp * CHUNK;
    if (j0 >= E) return;
    int j1 = min(j0 + CHUNK, E);

    const float4* hs = (LAYER == 1) ? g_hs1 : g_hs2;
    float4*       ag = (LAYER == 1) ? g_agg1 : g_agg2;

    int2 e = __ldg(&g_edges[j0]);
    int d_cur = e.y;
    int run_start = j0;
    float4 acc = __ldg(&hs[(size_t)e.x * 4 + q]);

#pragma unroll 5
    for (int j = j0 + 1; j < j1; j++) {
        int2 e2 = __ldg(&g_edges[j]);
        float4 v = __ldg(&hs[(size_t)e2.x * 4 + q]);
        if (e2.y != d_cur) {
            float4* p = &ag[(size_t)d_cur * 4 + q];
            if (run_start == j0) {
                red_add_v4(p, acc);                // left-boundary run
            } else {
                float4 self = __ldg(&hs[(size_t)d_cur * 4 + q]);
                acc.x += self.x; acc.y += self.y;
                acc.z += self.z; acc.w += self.w;
                *p = acc;                          // interior run: exclusive
            }
            d_cur = e2.y;
            run_start = j;
            acc = v;
        } else {
            acc.x += v.x; acc.y += v.y; acc.z += v.z; acc.w += v.w;
        }
    }
    red_add_v4(&ag[(size_t)d_cur * 4 + q], acc);   // right-boundary run
}

// ------------------------------------------- layer1 epilogue + layer2 xform -
__global__ void k_transform2(const float* __restrict__ W2,
                             const float* __restrict__ b1, int n) {
    __shared__ float sW[16][16];
    __shared__ float sb[16];
    int t = threadIdx.x;
    if (t < 256) sW[t >> 4][t & 15] = W2[t];
    if (t < 16) sb[t] = b1[t];
    __syncthreads();

    int i = blockIdx.x * blockDim.x + t;
    if (i >= n) return;

    float di = g_dinv[i];
    const float4* ap1 = &g_agg1[(size_t)i * 4];
    float hin[16];
#pragma unroll
    for (int q = 0; q < 4; q++) {
        float4 v = ap1[q];
        hin[4*q+0] = v.x; hin[4*q+1] = v.y; hin[4*q+2] = v.z; hin[4*q+3] = v.w;
    }
#pragma unroll
    for (int k = 0; k < 16; k++)
        hin[k] = fmaxf(fmaf(hin[k], di, sb[k]), 0.0f);   // *dinv + b1, relu

    float4* hp = &g_hs2[(size_t)i * 4];
    float4* ap = &g_agg2[(size_t)i * 4];
#pragma unroll
    for (int qq = 0; qq < 4; qq++) {
        float4 o;
        float* op = &o.x;
#pragma unroll
        for (int jj = 0; jj < 4; jj++) {
            int j = 4*qq + jj;
            float s = 0.0f;
#pragma unroll
            for (int k = 0; k < 16; k++) s = fmaf(hin[k], sW[k][j], s);
            op[jj] = s * di;
        }
        hp[qq] = o;
        ap[qq] = o;   // self-loop init
    }
}

// ------------------------------------------------------------- epilogue -----
__global__ void k_epilogue(float* __restrict__ out,
                           const float* __restrict__ b2, int n) {
    __shared__ float sb[16];
    int t = threadIdx.x;
    if (t < 16) sb[t] = b2[t];
    __syncthreads();

    int i = blockIdx.x * blockDim.x + t;
    if (i >= n) return;

    float di = g_dinv[i];
    const float4* ap = &g_agg2[(size_t)i * 4];
    float4* op = (float4*)(out + (size_t)i * FEAT);
#pragma unroll
    for (int q = 0; q < 4; q++) {
        float4 v = ap[q];
        v.x = fmaf(v.x, di, sb[4*q+0]);
        v.y = fmaf(v.y, di, sb[4*q+1]);
        v.z = fmaf(v.z, di, sb[4*q+2]);
        v.w = fmaf(v.w, di, sb[4*q+3]);
        op[q] = v;
    }
}

// ---------------------------------------------------------------- launch ----
extern "C" void kernel_launch(void* const* d_in, const int* in_sizes, int n_in,
                              void* d_out, int out_size) {
    const float* x    = (const float*)d_in[0];
    const int*   eidx = (const int*)  d_in[1];
    const float* W1   = (const float*)d_in[2];
    const float* b1   = (const float*)d_in[3];
    const float* W2   = (const float*)d_in[4];
    const float* b2   = (const float*)d_in[5];
    float* out = (float*)d_out;

    int n = in_sizes[0] / FEAT;       // 100000
    int E = in_sizes[1] / 2;          // 3200000
    const int* src = eidx;
    const int* dst = eidx + E;

    const int B = 256;
    int gn = (n + B - 1) / B;                     // node-parallel grid (391)
    int ge = (E + B - 1) / B;                     // edge-parallel grid
    int nb = gn;                                  // #scan blocks (<=512)
    long long nthr = ((long long)(E + CHUNK - 1) / CHUNK) * 4;
    int ga = (int)((nthr + B - 1) / B);           // segmented-agg grid

    // CSR build (once, shared by both layers)
    k_zero  <<<gn, B>>>(n);
    k_hist  <<<ge, B>>>(dst, E);
    k_scanA <<<nb, 256>>>(n);
    k_scanB <<<1, 512>>>(nb);
    k_scanC <<<gn, B>>>(n);
    k_bucket<<<ge, B>>>(src, dst, E);

    // Layer 1
    k_transform1<<<gn, B>>>(x, W1, n);
    k_aggseg<1> <<<ga, B>>>(E);
    // Layer 2
    k_transform2<<<gn, B>>>(W2, b1, n);
    k_aggseg<2> <<<ga, B>>>(E);
    k_epilogue  <<<gn, B>>>(out, b2, n);
}

// round 8
// speedup vs baseline: 1.1696x; 1.1612x over previous
#include <cuda_runtime.h>
#include <cuda_fp16.h>

#define N_NODES 100000
#define N_EDGES 3200000
#define FEAT 16

// Scratch in __device__ globals (no allocations allowed).
__device__ int   g_degi     [N_NODES];
__device__ int   g_scantmp  [N_NODES];
__device__ int   g_rowstart [N_NODES + 1];
__device__ int   g_cursor   [N_NODES];
__device__ int   g_blocksums[512];
__device__ int   g_esrc     [N_EDGES];        // src ids, dst-sorted
__device__ float g_dinv     [N_NODES];
__device__ uint2 g_hsh1     [N_NODES * 4];    // fp16x2-packed messages, 32B/node
__device__ uint2 g_hsh2     [N_NODES * 4];
__device__ float4 g_agg1    [N_NODES * 4];    // layer-1 aggregate (fp32)

// ---------------------------------------------------------------- degree ----
__global__ void k_zero(int n) {
    int i = blockIdx.x * blockDim.x + threadIdx.x;
    if (i < n) g_degi[i] = 0;
}

__global__ void k_hist(const int* __restrict__ dst, int E) {
    int e = blockIdx.x * blockDim.x + threadIdx.x;
    if (e < E) atomicAdd(&g_degi[dst[e]], 1);
}

// ------------------------------------------------------ shuffle-based scan --
__global__ void k_scanA(int n) {                 // 1024-thread tiles
    __shared__ int wsum[32];
    int t = threadIdx.x;
    int idx = blockIdx.x * 1024 + t;
    int v = (idx < n) ? g_degi[idx] : 0;
    int lane = t & 31, wid = t >> 5;

    int s = v;
#pragma unroll
    for (int off = 1; off < 32; off <<= 1) {
        int u = __shfl_up_sync(0xffffffffu, s, off);
        if (lane >= off) s += u;
    }
    if (lane == 31) wsum[wid] = s;
    __syncthreads();
    if (wid == 0) {
        int ws = wsum[lane];
#pragma unroll
        for (int off = 1; off < 32; off <<= 1) {
            int u = __shfl_up_sync(0xffffffffu, ws, off);
            if (lane >= off) ws += u;
        }
        wsum[lane] = ws;
    }
    __syncthreads();
    int incl = s + ((wid > 0) ? wsum[wid - 1] : 0);
    if (idx < n) g_scantmp[idx] = incl - v;      // block-local exclusive
    if (t == 1023) g_blocksums[blockIdx.x] = incl;
}

__global__ void k_scanB(int nb) {                // nb <= 128
    __shared__ int wsum[4];
    int t = threadIdx.x;                          // 128 threads
    int lane = t & 31, wid = t >> 5;
    int v = (t < nb) ? g_blocksums[t] : 0;
    int s = v;
#pragma unroll
    for (int off = 1; off < 32; off <<= 1) {
        int u = __shfl_up_sync(0xffffffffu, s, off);
        if (lane >= off) s += u;
    }
    if (lane == 31) wsum[wid] = s;
    __syncthreads();
    int add = 0;
#pragma unroll
    for (int w = 0; w < 4; w++) if (w < wid) add += wsum[w];
    if (t < nb) g_blocksums[t] = s + add - v;    // exclusive
}

__global__ void k_scanC(int n, int E) {
    int idx = blockIdx.x * blockDim.x + threadIdx.x;
    if (idx < n) {
        int r = g_scantmp[idx] + g_blocksums[idx >> 10];
        g_rowstart[idx] = r;
        g_cursor[idx]   = r;
    }
    if (idx == 0) g_rowstart[n] = E;
}

// ----------------------------------------------------------------- bucket ---
__global__ void k_bucket(const int* __restrict__ src,
                         const int* __restrict__ dst, int E) {
    int e = blockIdx.x * blockDim.x + threadIdx.x;
    if (e >= E) return;
    int d = dst[e];
    int pos = atomicAdd(&g_cursor[d], 1);
    g_esrc[pos] = src[e];
}

// ---------------------------------------------------------- layer 1 xform ----
__global__ void k_transform1(const float* __restrict__ x,
                             const float* __restrict__ W, int n) {
    __shared__ float sW[16][16];
    int t = threadIdx.x;
    if (t < 256) sW[t >> 4][t & 15] = W[t];
    __syncthreads();

    int i = blockIdx.x * blockDim.x + t;
    if (i >= n) return;

    float di = rsqrtf((float)g_degi[i] + 1.0f);   // +1 self loop
    g_dinv[i] = di;

    const float4* xr = (const float4*)(x + (size_t)i * FEAT);
    float xin[16];
#pragma unroll
    for (int q = 0; q < 4; q++) {
        float4 v = xr[q];
        xin[4*q+0] = v.x; xin[4*q+1] = v.y; xin[4*q+2] = v.z; xin[4*q+3] = v.w;
    }

    uint2* hp = &g_hsh1[(size_t)i * 4];
#pragma unroll
    for (int qq = 0; qq < 4; qq++) {
        float o[4];
#pragma unroll
        for (int jj = 0; jj < 4; jj++) {
            int j = 4*qq + jj;
            float s = 0.0f;
#pragma unroll
            for (int k = 0; k < 16; k++) s = fmaf(xin[k], sW[k][j], s);
            o[jj] = s * di;
        }
        __half2 p0 = __floats2half2_rn(o[0], o[1]);
        __half2 p1 = __floats2half2_rn(o[2], o[3]);
        hp[qq] = make_uint2(*(unsigned*)&p0, *(unsigned*)&p1);
    }
}

// ------------------------------------------------------------- aggregate ----
// One warp per node; lanes = 8 edge-slots x 4 feature-quarters.
// fp16 gather (32B/edge = 1 sector), fp32 register accumulation, shfl
// reduction, one plain store per node. Zero atomics.
template <int LAYER>
__global__ void k_agg(const float* __restrict__ b2,
                      float* __restrict__ out, int n) {
    int gw   = (blockIdx.x * blockDim.x + threadIdx.x) >> 5;
    int lane = threadIdx.x & 31;
    if (gw >= n) return;
    int q    = lane & 3;
    int slot = lane >> 2;

    int beg = g_rowstart[gw];
    int end = g_rowstart[gw + 1];
    const uint2* hs = (LAYER == 1) ? g_hsh1 : g_hsh2;

    float4 acc = make_float4(0.f, 0.f, 0.f, 0.f);
#pragma unroll 2
    for (int j = beg + slot; j < end; j += 8) {
        int s = __ldg(&g_esrc[j]);
        uint2 w = __ldg(&hs[(size_t)s * 4 + q]);
        float2 f0 = __half22float2(*(__half2*)&w.x);
        float2 f1 = __half22float2(*(__half2*)&w.y);
        acc.x += f0.x; acc.y += f0.y; acc.z += f1.x; acc.w += f1.y;
    }
#pragma unroll
    for (int off = 16; off >= 4; off >>= 1) {
        acc.x += __shfl_down_sync(0xffffffffu, acc.x, off);
        acc.y += __shfl_down_sync(0xffffffffu, acc.y, off);
        acc.z += __shfl_down_sync(0xffffffffu, acc.z, off);
        acc.w += __shfl_down_sync(0xffffffffu, acc.w, off);
    }
    if (lane < 4) {
        uint2 sw = __ldg(&hs[(size_t)gw * 4 + lane]);    // self loop
        float2 s0 = __half22float2(*(__half2*)&sw.x);
        float2 s1 = __half22float2(*(__half2*)&sw.y);
        acc.x += s0.x; acc.y += s0.y; acc.z += s1.x; acc.w += s1.y;
        if (LAYER == 1) {
            g_agg1[(size_t)gw * 4 + lane] = acc;
        } else {
            float di = g_dinv[gw];
            float4 bb = __ldg(((const float4*)b2) + lane);
            acc.x = fmaf(acc.x, di, bb.x);
            acc.y = fmaf(acc.y, di, bb.y);
            acc.z = fmaf(acc.z, di, bb.z);
            acc.w = fmaf(acc.w, di, bb.w);
            ((float4*)out)[(size_t)gw * 4 + lane] = acc;
        }
    }
}

// ------------------------------------------- layer1 epilogue + layer2 xform -
__global__ void k_transform2(const float* __restrict__ W2,
                             const float* __restrict__ b1, int n) {
    __shared__ float sW[16][16];
    __shared__ float sb[16];
    int t = threadIdx.x;
    if (t < 256) sW[t >> 4][t & 15] = W2[t];
    if (t < 16) sb[t] = b1[t];
    __syncthreads();

    int i = blockIdx.x * blockDim.x + t;
    if (i >= n) return;

    float di = g_dinv[i];
    const float4* ap1 = &g_agg1[(size_t)i * 4];
    float hin[16];
#pragma unroll
    for (int q = 0; q < 4; q++) {
        float4 v = ap1[q];
        hin[4*q+0] = v.x; hin[4*q+1] = v.y; hin[4*q+2] = v.z; hin[4*q+3] = v.w;
    }
#pragma unroll
    for (int k = 0; k < 16; k++)
        hin[k] = fmaxf(fmaf(hin[k], di, sb[k]), 0.0f);   // *dinv + b1, relu

    uint2* hp = &g_hsh2[(size_t)i * 4];
#pragma unroll
    for (int qq = 0; qq < 4; qq++) {
        float o[4];
#pragma unroll
        for (int jj = 0; jj < 4; jj++) {
            int j = 4*qq + jj;
            float s = 0.0f;
#pragma unroll
            for (int k = 0; k < 16; k++) s = fmaf(hin[k], sW[k][j], s);
            o[jj] = s * di;
        }
        __half2 p0 = __floats2half2_rn(o[0], o[1]);
        __half2 p1 = __floats2half2_rn(o[2], o[3]);
        hp[qq] = make_uint2(*(unsigned*)&p0, *(unsigned*)&p1);
    }
}

// ---------------------------------------------------------------- launch ----
extern "C" void kernel_launch(void* const* d_in, const int* in_sizes, int n_in,
                              void* d_out, int out_size) {
    const float* x    = (const float*)d_in[0];
    const int*   eidx = (const int*)  d_in[1];
    const float* W1   = (const float*)d_in[2];
    const float* b1   = (const float*)d_in[3];
    const float* W2   = (const float*)d_in[4];
    const float* b2   = (const float*)d_in[5];
    float* out = (float*)d_out;

    int n = in_sizes[0] / FEAT;       // 100000
    int E = in_sizes[1] / 2;          // 3200000
    const int* src = eidx;
    const int* dst = eidx + E;

    const int B = 256;
    int gn  = (n + B - 1) / B;        // node-parallel grid
    int ge  = (E + B - 1) / B;        // edge-parallel grid
    int nbA = (n + 1023) / 1024;      // scanA blocks (98)
    int gw  = (n * 32 + B - 1) / B;   // warp-per-node grid

    // CSR build (shared by both layers)
    k_zero  <<<gn, B>>>(n);
    k_hist  <<<ge, B>>>(dst, E);
    k_scanA <<<nbA, 1024>>>(n);
    k_scanB <<<1, 128>>>(nbA);
    k_scanC <<<gn, B>>>(n, E);
    k_bucket<<<ge, B>>>(src, dst, E);

    // Layer 1
    k_transform1<<<gn, B>>>(x, W1, n);
    k_agg<1>    <<<gw, B>>>(nullptr, nullptr, n);
    // Layer 2 (epilogue fused into aggregate)
    k_transform2<<<gn, B>>>(W2, b1, n);
    k_agg<2>    <<<gw, B>>>(b2, out, n);
}